// round 11
// baseline (speedup 1.0000x reference)
#include <cuda_runtime.h>

#define T_LEN 4096
#define B_SZ  512
#define NIN   42
#define NH    9
#define STRIDE (B_SZ * NH)   // 4608 floats per timestep (output)
#define EPB   4              // batch elements per block
#define NBLK  (B_SZ / EPB)   // 128 blocks
#define CH    16             // timesteps per chunk
#define NCH   (T_LEN / CH)   // 256

typedef unsigned long long ull;

// ---------------------------------------------------------------------------
// helpers
// ---------------------------------------------------------------------------
__device__ __forceinline__ ull ffma2(ull a, ull b, ull c) {
    ull d;
    asm("fma.rn.f32x2 %0, %1, %2, %3;" : "=l"(d) : "l"(a), "l"(b), "l"(c));
    return d;
}
__device__ __forceinline__ ull pack2(float a, float b) {
    ull r;
    asm("mov.b64 %0, {%1,%2};" : "=l"(r) : "f"(a), "f"(b));
    return r;
}
__device__ __forceinline__ void lds_v2u64(ull& a, ull& b, const void* p) {
    unsigned addr = (unsigned)__cvta_generic_to_shared(p);
    asm volatile("ld.shared.v2.u64 {%0,%1}, [%2];" : "=l"(a), "=l"(b) : "r"(addr));
}
__device__ __forceinline__ ull lds_u64(const void* p) {
    unsigned addr = (unsigned)__cvta_generic_to_shared(p);
    ull v;
    asm volatile("ld.shared.u64 %0, [%1];" : "=l"(v) : "r"(addr));
    return v;
}
__device__ __forceinline__ float tanh_ap(float x) {
    float y;
    asm("tanh.approx.f32 %0, %1;" : "=f"(y) : "f"(x));
    return y;
}
__device__ __forceinline__ int ld_acq_sh(const int* p) {
    unsigned a = (unsigned)__cvta_generic_to_shared(p);
    int v;
    asm volatile("ld.acquire.cta.shared.b32 %0, [%1];" : "=r"(v) : "r"(a));
    return v;
}
__device__ __forceinline__ int ld_vol_sh(const int* p) {
    unsigned a = (unsigned)__cvta_generic_to_shared(p);
    int v;
    asm volatile("ld.volatile.shared.b32 %0, [%1];" : "=r"(v) : "r"(a));
    return v;
}
__device__ __forceinline__ void st_rel_sh(int* p, int v) {
    unsigned a = (unsigned)__cvta_generic_to_shared(p);
    asm volatile("st.release.cta.shared.b32 [%0], %1;" :: "r"(a), "r"(v) : "memory");
}
__device__ __forceinline__ void red_rel_sh(int* p, int v) {
    unsigned a = (unsigned)__cvta_generic_to_shared(p);
    asm volatile("red.release.cta.shared.add.u32 [%0], %1;" :: "r"(a), "r"(v) : "memory");
}

// XP: x = i/2, y = f/2, z = g, w = o/2 (weights/biases pre-halved).
#define LSTM_STEP(XP, TT) do {                                                \
    float a0 = (XP).x, a1 = (XP).y, a2 = (XP).z, a3 = (XP).w;                 \
    float d0 = 0.f, d1 = 0.f, d2 = 0.f, d3 = 0.f;                             \
    _Pragma("unroll")                                                         \
    for (int k = 0; k < 9; k++) {                                             \
        float hk = __shfl_sync(0xFFFFFFFFu, h, k);                            \
        if (k < 5) {                                                          \
            a0 = fmaf(Wi[k], hk, a0); a1 = fmaf(Wf[k], hk, a1);               \
            a2 = fmaf(Wg[k], hk, a2); a3 = fmaf(Wo[k], hk, a3);               \
        } else {                                                              \
            d0 = fmaf(Wi[k], hk, d0); d1 = fmaf(Wf[k], hk, d1);               \
            d2 = fmaf(Wg[k], hk, d2); d3 = fmaf(Wo[k], hk, d3);               \
        }                                                                     \
    }                                                                         \
    float ig = fmaf(0.5f, tanh_ap(a0 + d0), 0.5f);                            \
    float fg = fmaf(0.5f, tanh_ap(a1 + d1), 0.5f);                            \
    float gg = tanh_ap(a2 + d2);                                              \
    float og = fmaf(0.5f, tanh_ap(a3 + d3), 0.5f);                            \
    c = fmaf(fg, c, ig * gg);                                                 \
    h = og * tanh_ap(c);                                                      \
    if (valid) out[(TT) * STRIDE + base_idx] = h;                             \
} while (0)

// ---------------------------------------------------------------------------
// Fused kernel: warps 0-3 produce gates for this block's 4 batch elems
// (x held in registers, gates written to smem ring); warps 4-7 run the
// recurrence with a software-pipelined gbuf load.
// ---------------------------------------------------------------------------
__global__ __launch_bounds__(256, 1) void lstm_fused_kernel(
    const float* __restrict__ x,    const float* __restrict__ h_in,
    const float* __restrict__ c_in, const float* __restrict__ Wih,
    const float* __restrict__ Whh,  const float* __restrict__ bih,
    const float* __restrict__ bhh,  float* __restrict__ out)
{
    __shared__ float4 gbuf[2][CH][EPB * NH];   // gate ring: 18432 B
    __shared__ float2 wsH[2][NIN][10];         // paired W_ih: 6720 B
    __shared__ int ready, done;

    const int tid  = threadIdx.x;
    const int w    = tid >> 5;
    const int lane = tid & 31;
    const int b0   = blockIdx.x * EPB;

    // stage paired, pre-scaled W_ih: wsH[h][k][j] = (W[2h][j][k], W[2h+1][j][k])
    for (int i = tid; i < NIN * 18; i += 256) {
        int k = i / 18, rem = i - 18 * k;
        int hh = rem / 9, j = rem - 9 * hh;
        float w0 = Wih[((2 * hh) * NH + j) * NIN + k];
        float w1 = Wih[((2 * hh + 1) * NH + j) * NIN + k];
        if (hh == 0) { w0 *= 0.5f; w1 *= 0.5f; }   // i, f
        else         { w1 *= 0.5f; }               // o
        wsH[hh][k][j] = make_float2(w0, w1);
    }
    if (tid == 0) { ready = 0; done = 0; }
    __syncthreads();

    if (w >= EPB) {
        // ====================== COMPUTE WARP (wid 4-7, 1 elem) ===============
        const int cw = w - EPB;           // batch slot 0..3
        const int b  = b0 + cw;
        const int j  = (lane < 9) ? lane : 8;
        const bool valid = (lane < 9);

        float Wi[NH], Wf[NH], Wg[NH], Wo[NH];
        #pragma unroll
        for (int k = 0; k < NH; k++) {
            Wi[k] = 0.5f * Whh[(0 * NH + j) * NH + k];
            Wf[k] = 0.5f * Whh[(1 * NH + j) * NH + k];
            Wg[k] =        Whh[(2 * NH + j) * NH + k];
            Wo[k] = 0.5f * Whh[(3 * NH + j) * NH + k];
        }
        float h = h_in[b * NH + j];
        float c = c_in[b * NH + j];
        const int base_idx = b * NH + j;
        const int u = cw * NH + j;

        for (int cch = 0; cch < NCH; cch++) {
            const int buf = cch & 1;
            const int t0  = cch * CH;
            if (ld_acq_sh(&ready) < cch + 1) {
                while (ld_acq_sh(&ready) < cch + 1) __nanosleep(32);
            }
            const float4* xb = &gbuf[buf][0][u];
            // software-pipelined: LDS for step s+1 issued before step s math
            float4 xp = xb[0];
            #pragma unroll
            for (int s = 0; s < CH; s++) {
                float4 xn = xp;
                if (s + 1 < CH) xn = xb[(s + 1) * (EPB * NH)];
                LSTM_STEP(xp, t0 + s);
                xp = xn;
            }
            __syncwarp();
            if (lane == 0) red_rel_sh(&done, 1);
        }

        if (valid) {
            out[(size_t)T_LEN * STRIDE + base_idx]          = h;  // hn
            out[(size_t)T_LEN * STRIDE + STRIDE + base_idx] = c;  // cn
        }
    } else {
        // ====================== PRODUCER WARP (wid 0-3) ======================
        // Warp w: gate-half (w&1), rows (w>>1)*32+lane. Lane owns ONE (t,b)
        // row; its 42 x values live in 21 float2 registers (double-buffered).
        const int half = w & 1;
        const int row  = (w >> 1) * 32 + lane;   // 0..63 within chunk
        const int tl   = row >> 2;               // local t
        const int bb   = row & 3;                // batch slot

        // folded, pre-scaled biases
        ull bias[9];
        #pragma unroll
        for (int j = 0; j < 9; j++) {
            float bb0 = bih[(2 * half) * NH + j]     + bhh[(2 * half) * NH + j];
            float bb1 = bih[(2 * half + 1) * NH + j] + bhh[(2 * half + 1) * NH + j];
            if (half == 0) { bb0 *= 0.5f; bb1 *= 0.5f; }
            else           { bb1 *= 0.5f; }
            bias[j] = pack2(bb0, bb1);
        }

        // x source for this lane's row at chunk cch:
        //   x + ((cch*CH + tl)*B_SZ + b0 + bb)*NIN, as 21 float2 (168B, aligned)
        const float2* xsrc = (const float2*)
            (x + ((size_t)tl * B_SZ + (b0 + bb)) * NIN);
        const size_t chstep = (size_t)CH * B_SZ * NIN / 2;  // float2 per chunk

        float2 xcur[21], xnxt[21];
        #pragma unroll
        for (int q = 0; q < 21; q++) xcur[q] = xsrc[q];

        for (int cch = 0; cch < NCH; cch++) {
            const int buf = cch & 1;

            // prefetch next chunk's x (LDG latency overlaps the mainloop)
            if (cch + 1 < NCH) {
                const float2* src = xsrc + (size_t)(cch + 1) * chstep;
                #pragma unroll
                for (int q = 0; q < 21; q++) xnxt[q] = src[q];
            }

            // wait until gbuf[buf] (chunk cch-2) fully consumed
            if (cch >= 2) {
                const int need = EPB * (cch - 1);
                if (ld_vol_sh(&done) < need) {
                    while (ld_vol_sh(&done) < need) __nanosleep(64);
                }
            }

            // mainloop over k (x from registers, weights from smem broadcast)
            ull acc[9];
            #pragma unroll
            for (int j = 0; j < 9; j++) acc[j] = bias[j];

            const float*  xf = (const float*)xcur;
            const float2* wb = &wsH[half][0][0];
            #pragma unroll
            for (int k = 0; k < NIN; k++) {
                float xv = xf[k];
                ull xx = pack2(xv, xv);
                const float2* wk = wb + (size_t)k * 10;
                ull wj[9];
                lds_v2u64(wj[0], wj[1], wk);
                lds_v2u64(wj[2], wj[3], wk + 2);
                lds_v2u64(wj[4], wj[5], wk + 4);
                lds_v2u64(wj[6], wj[7], wk + 6);
                wj[8] = lds_u64(wk + 8);
                #pragma unroll
                for (int j = 0; j < 9; j++) acc[j] = ffma2(wj[j], xx, acc[j]);
            }

            // epilogue: write gate pairs into gbuf[buf][tl][bb*9+j] half-slot
            {
                ull* base = (ull*)&gbuf[buf][tl][bb * NH] + half;
                #pragma unroll
                for (int j = 0; j < 9; j++) base[2 * j] = acc[j];
            }
            asm volatile("bar.sync 1, 128;" ::: "memory");
            if (tid == 0) st_rel_sh(&ready, cch + 1);

            // rotate x register buffers
            if (cch + 1 < NCH) {
                #pragma unroll
                for (int q = 0; q < 21; q++) xcur[q] = xnxt[q];
            }
        }
    }
}

// ---------------------------------------------------------------------------
extern "C" void kernel_launch(void* const* d_in, const int* in_sizes, int n_in,
                              void* d_out, int out_size) {
    const float* x   = (const float*)d_in[0];
    const float* h   = (const float*)d_in[1];
    const float* c   = (const float*)d_in[2];
    const float* Wih = (const float*)d_in[3];
    const float* Whh = (const float*)d_in[4];
    const float* bih = (const float*)d_in[5];
    const float* bhh = (const float*)d_in[6];
    float* out = (float*)d_out;

    lstm_fused_kernel<<<NBLK, 256>>>(x, h, c, Wih, Whh, bih, bhh, out);
}

// round 12
// speedup vs baseline: 1.2264x; 1.2264x over previous
#include <cuda_runtime.h>

#define T_LEN 4096
#define B_SZ  512
#define NIN   42
#define NH    9
#define STRIDE (B_SZ * NH)   // 4608 floats per timestep (output)
#define EPB   4              // batch elements per block
#define NBLK  (B_SZ / EPB)   // 128 blocks
#define CH    16             // timesteps per chunk
#define NCH   (T_LEN / CH)   // 256
#define XSP   65             // padded row stride in xs

typedef unsigned long long ull;

// ---------------------------------------------------------------------------
// helpers
// ---------------------------------------------------------------------------
__device__ __forceinline__ ull ffma2(ull a, ull b, ull c) {
    ull d;
    asm("fma.rn.f32x2 %0, %1, %2, %3;" : "=l"(d) : "l"(a), "l"(b), "l"(c));
    return d;
}
__device__ __forceinline__ ull pack2(float a, float b) {
    ull r;
    asm("mov.b64 %0, {%1,%2};" : "=l"(r) : "f"(a), "f"(b));
    return r;
}
__device__ __forceinline__ void lds_v2u64(ull& a, ull& b, const void* p) {
    unsigned addr = (unsigned)__cvta_generic_to_shared(p);
    asm volatile("ld.shared.v2.u64 {%0,%1}, [%2];" : "=l"(a), "=l"(b) : "r"(addr));
}
__device__ __forceinline__ ull lds_u64(const void* p) {
    unsigned addr = (unsigned)__cvta_generic_to_shared(p);
    ull v;
    asm volatile("ld.shared.u64 %0, [%1];" : "=l"(v) : "r"(addr));
    return v;
}
__device__ __forceinline__ float2 unpack2(ull v) {
    float2 f;
    f.x = __uint_as_float((unsigned)(v & 0xffffffffull));
    f.y = __uint_as_float((unsigned)(v >> 32));
    return f;
}
__device__ __forceinline__ float tanh_ap(float x) {
    float y;
    asm("tanh.approx.f32 %0, %1;" : "=f"(y) : "f"(x));
    return y;
}
__device__ __forceinline__ int ld_acq_sh(const int* p) {
    unsigned a = (unsigned)__cvta_generic_to_shared(p);
    int v;
    asm volatile("ld.acquire.cta.shared.b32 %0, [%1];" : "=r"(v) : "r"(a));
    return v;
}
__device__ __forceinline__ int ld_vol_sh(const int* p) {
    unsigned a = (unsigned)__cvta_generic_to_shared(p);
    int v;
    asm volatile("ld.volatile.shared.b32 %0, [%1];" : "=r"(v) : "r"(a));
    return v;
}
__device__ __forceinline__ void st_rel_sh(int* p, int v) {
    unsigned a = (unsigned)__cvta_generic_to_shared(p);
    asm volatile("st.release.cta.shared.b32 [%0], %1;" :: "r"(a), "r"(v) : "memory");
}
__device__ __forceinline__ void red_rel_sh(int* p, int v) {
    unsigned a = (unsigned)__cvta_generic_to_shared(p);
    asm volatile("red.release.cta.shared.add.u32 [%0], %1;" :: "r"(a), "r"(v) : "memory");
}

// Packed step: P01=(i/2,f/2)+bias, P23=(g,o/2)+bias pre-accumulated upstream.
// W01[k]=(Wi/2,Wf/2), W23[k]=(Wg,Wo/2).
#define LSTM_STEP_P(P01, P23, TT) do {                                        \
    ull a01 = (P01), a23 = (P23);                                             \
    _Pragma("unroll")                                                         \
    for (int k = 0; k < 9; k++) {                                             \
        float hk = __shfl_sync(0xFFFFFFFFu, h, k);                            \
        ull hh = pack2(hk, hk);                                               \
        a01 = ffma2(W01[k], hh, a01);                                         \
        a23 = ffma2(W23[k], hh, a23);                                         \
    }                                                                         \
    float2 v0 = unpack2(a01);                                                 \
    float2 v1 = unpack2(a23);                                                 \
    float ig = fmaf(0.5f, tanh_ap(v0.x), 0.5f);                               \
    float fg = fmaf(0.5f, tanh_ap(v0.y), 0.5f);                               \
    float gg = tanh_ap(v1.x);                                                 \
    float og = fmaf(0.5f, tanh_ap(v1.y), 0.5f);                               \
    c = fmaf(fg, c, ig * gg);                                                 \
    h = og * tanh_ap(c);                                                      \
    if (valid) out[(TT) * STRIDE + base_idx] = h;                             \
} while (0)

// ---------------------------------------------------------------------------
// Fused kernel: warps 0-3 produce gates for this block's 4 batch elems
// (x staged in smem, R10-style); warps 4-7 run the packed recurrence.
// ---------------------------------------------------------------------------
__global__ __launch_bounds__(256, 1) void lstm_fused_kernel(
    const float* __restrict__ x,    const float* __restrict__ h_in,
    const float* __restrict__ c_in, const float* __restrict__ Wih,
    const float* __restrict__ Whh,  const float* __restrict__ bih,
    const float* __restrict__ bhh,  float* __restrict__ out)
{
    __shared__ float4 gbuf[2][CH][EPB * NH];   // gate ring: 18432 B
    __shared__ float  xs[2][NIN][XSP];         // x staging: 21840 B (k-major)
    __shared__ float2 wsH[2][NIN][10];         // paired W_ih: 6720 B
    __shared__ int ready, done;

    const int tid  = threadIdx.x;
    const int w    = tid >> 5;
    const int lane = tid & 31;
    const int b0   = blockIdx.x * EPB;

    // stage paired, pre-scaled W_ih: wsH[h][k][j] = (W[2h][j][k], W[2h+1][j][k])
    for (int i = tid; i < NIN * 18; i += 256) {
        int k = i / 18, rem = i - 18 * k;
        int hh = rem / 9, j = rem - 9 * hh;
        float w0 = Wih[((2 * hh) * NH + j) * NIN + k];
        float w1 = Wih[((2 * hh + 1) * NH + j) * NIN + k];
        if (hh == 0) { w0 *= 0.5f; w1 *= 0.5f; }   // i, f
        else         { w1 *= 0.5f; }               // o
        wsH[hh][k][j] = make_float2(w0, w1);
    }
    if (tid == 0) { ready = 0; done = 0; }
    __syncthreads();

    if (w >= EPB) {
        // ====================== COMPUTE WARP (wid 4-7, 1 elem) ===============
        const int cw = w - EPB;           // batch slot 0..3
        const int b  = b0 + cw;
        const int j  = (lane < 9) ? lane : 8;
        const bool valid = (lane < 9);

        // paired recurrent weights
        ull W01[NH], W23[NH];
        #pragma unroll
        for (int k = 0; k < NH; k++) {
            W01[k] = pack2(0.5f * Whh[(0 * NH + j) * NH + k],
                           0.5f * Whh[(1 * NH + j) * NH + k]);
            W23[k] = pack2(       Whh[(2 * NH + j) * NH + k],
                           0.5f * Whh[(3 * NH + j) * NH + k]);
        }
        float h = h_in[b * NH + j];
        float c = c_in[b * NH + j];
        const int base_idx = b * NH + j;
        const int u = cw * NH + j;

        for (int cch = 0; cch < NCH; cch++) {
            const int buf = cch & 1;
            const int t0  = cch * CH;
            if (ld_acq_sh(&ready) < cch + 1) {
                while (ld_acq_sh(&ready) < cch + 1) __nanosleep(32);
            }
            const float4* xb = &gbuf[buf][0][u];
            // software-pipelined gate loads
            ull p01, p23, n01, n23;
            lds_v2u64(p01, p23, xb);
            #pragma unroll
            for (int s = 0; s < CH; s++) {
                if (s + 1 < CH) lds_v2u64(n01, n23, xb + (s + 1) * (EPB * NH));
                LSTM_STEP_P(p01, p23, t0 + s);
                p01 = n01; p23 = n23;
            }
            __syncwarp();
            if (lane == 0) red_rel_sh(&done, 1);
        }

        if (valid) {
            out[(size_t)T_LEN * STRIDE + base_idx]          = h;  // hn
            out[(size_t)T_LEN * STRIDE + STRIDE + base_idx] = c;  // cn
        }
    } else {
        // ====================== PRODUCER WARP (wid 0-3) ======================
        // Warp w: gate-half (w&1), row (w>>1)*32+lane within chunk (64 rows).
        const int half = w & 1;
        const int row  = (w >> 1) * 32 + lane;   // 0..63
        const int tl   = row >> 2;               // local t
        const int bb   = row & 3;                // batch slot

        // folded, pre-scaled biases
        ull bias[9];
        #pragma unroll
        for (int j = 0; j < 9; j++) {
            float bb0 = bih[(2 * half) * NH + j]     + bhh[(2 * half) * NH + j];
            float bb1 = bih[(2 * half + 1) * NH + j] + bhh[(2 * half + 1) * NH + j];
            if (half == 0) { bb0 *= 0.5f; bb1 *= 0.5f; }
            else           { bb1 *= 0.5f; }
            bias[j] = pack2(bb0, bb1);
        }

        // x staging roles: staging row sr = tid>>1 (0..63), part sp = tid&1
        const int sr = tid >> 1;
        const int sp = tid & 1;
        const int k2base = sp * 10;          // float2 indices k2base..k2base+10
        const float2* xsrc0 = (const float2*)
            (x + ((size_t)(sr >> 2) * B_SZ + (b0 + (sr & 3))) * NIN) + k2base;
        const size_t chstep = (size_t)CH * B_SZ * NIN / 2;  // float2 per chunk

        // prologue: stage chunk 0
        {
            float2 xr[11];
            #pragma unroll
            for (int q = 0; q < 11; q++) xr[q] = xsrc0[q];
            #pragma unroll
            for (int q = 0; q < 11; q++) {
                xs[0][2 * (k2base + q)][sr]     = xr[q].x;
                xs[0][2 * (k2base + q) + 1][sr] = xr[q].y;
            }
            asm volatile("bar.sync 1, 128;" ::: "memory");
        }

        for (int cch = 0; cch < NCH; cch++) {
            const int buf  = cch & 1;
            const int nbuf = buf ^ 1;

            // prefetch next chunk's x into registers (LDG overlaps mainloop)
            float2 xr[11];
            if (cch + 1 < NCH) {
                const float2* src = xsrc0 + (size_t)(cch + 1) * chstep;
                #pragma unroll
                for (int q = 0; q < 11; q++) xr[q] = src[q];
            }

            // wait until gbuf[buf] (chunk cch-2) fully consumed
            if (cch >= 2) {
                const int need = EPB * (cch - 1);
                if (ld_vol_sh(&done) < need) {
                    while (ld_vol_sh(&done) < need) __nanosleep(64);
                }
            }

            // mainloop over k
            ull acc[9];
            #pragma unroll
            for (int j = 0; j < 9; j++) acc[j] = bias[j];

            const float*  xb = &xs[buf][0][row];
            const float2* wb = &wsH[half][0][0];
            #pragma unroll
            for (int k = 0; k < NIN; k++) {
                float xv = xb[(size_t)k * XSP];
                ull xx = pack2(xv, xv);
                const float2* wk = wb + (size_t)k * 10;
                ull wj[9];
                lds_v2u64(wj[0], wj[1], wk);
                lds_v2u64(wj[2], wj[3], wk + 2);
                lds_v2u64(wj[4], wj[5], wk + 4);
                lds_v2u64(wj[6], wj[7], wk + 6);
                wj[8] = lds_u64(wk + 8);
                #pragma unroll
                for (int j = 0; j < 9; j++) acc[j] = ffma2(wj[j], xx, acc[j]);
            }

            // epilogue: write gate pairs into gbuf[buf][tl][bb*9+j] half-slot
            {
                ull* base = (ull*)&gbuf[buf][tl][bb * NH] + half;
                #pragma unroll
                for (int j = 0; j < 9; j++) base[2 * j] = acc[j];
            }
            asm volatile("bar.sync 1, 128;" ::: "memory");
            if (tid == 0) st_rel_sh(&ready, cch + 1);

            // stage next chunk's x from registers
            if (cch + 1 < NCH) {
                #pragma unroll
                for (int q = 0; q < 11; q++) {
                    xs[nbuf][2 * (k2base + q)][sr]     = xr[q].x;
                    xs[nbuf][2 * (k2base + q) + 1][sr] = xr[q].y;
                }
                asm volatile("bar.sync 1, 128;" ::: "memory");
            }
        }
    }
}

// ---------------------------------------------------------------------------
extern "C" void kernel_launch(void* const* d_in, const int* in_sizes, int n_in,
                              void* d_out, int out_size) {
    const float* x   = (const float*)d_in[0];
    const float* h   = (const float*)d_in[1];
    const float* c   = (const float*)d_in[2];
    const float* Wih = (const float*)d_in[3];
    const float* Whh = (const float*)d_in[4];
    const float* bih = (const float*)d_in[5];
    const float* bhh = (const float*)d_in[6];
    float* out = (float*)d_out;

    lstm_fused_kernel<<<NBLK, 256>>>(x, h, c, Wih, Whh, bih, bhh, out);
}